// round 13
// baseline (speedup 1.0000x reference)
#include <cuda_runtime.h>
#include <cuda_bf16.h>
#include <cstdint>

// Problem constants (fixed by the reference)
#define MAXN   50000
#define MAXE   800000
#define IN_F   256
#define HID    64
#define HEADS  4
#define OUT_F  64
#define F0     (HEADS*HID)   // 256
#define F1     OUT_F         // 64
#define NEG_SLOPE 0.2f

// ---------------- static scratch (no allocations allowed) ----------------
__device__ float g_h0  [(size_t)MAXN * F0];   // x @ W0^T
__device__ float g_agg0[(size_t)MAXN * F0];   // layer-0 GAT output (pre-relu)
__device__ float g_h1  [(size_t)MAXN * F1];   // relu(agg0) @ W1^T
__device__ float g_e   [(size_t)MAXE * HEADS];// per-edge normalized alpha
__device__ float g_el  [(size_t)MAXN * HEADS];
__device__ float g_er  [(size_t)MAXN * HEADS];
__device__ int   g_cnt [MAXN];
__device__ int   g_rowptr[MAXN + 1];
__device__ int   g_wpos[MAXN];
__device__ int   g_srcsorted[MAXE];           // src node id of each edge, sorted by dst

// ---------------- CSR build ----------------
__global__ void count_kernel(const int* __restrict__ dst, int e) {
    int i = blockIdx.x * blockDim.x + threadIdx.x;
    if (i < e) atomicAdd(&g_cnt[dst[i]], 1);
}

// single-block exclusive scan of g_cnt[0..n) -> g_rowptr[0..n], copy to g_wpos
__global__ void scan_kernel(int n) {
    __shared__ int warp_sums[32];
    const int tid  = threadIdx.x;
    const int lane = tid & 31;
    const int wid  = tid >> 5;
    int carry = 0;
    for (int base = 0; base < n; base += 1024) {
        int i = base + tid;
        int v = (i < n) ? g_cnt[i] : 0;
        int incl = v;
        #pragma unroll
        for (int o = 1; o < 32; o <<= 1) {
            int t = __shfl_up_sync(0xFFFFFFFFu, incl, o);
            if (lane >= o) incl += t;
        }
        if (lane == 31) warp_sums[wid] = incl;
        __syncthreads();
        if (wid == 0) {
            int x = warp_sums[lane];
            #pragma unroll
            for (int o = 1; o < 32; o <<= 1) {
                int t = __shfl_up_sync(0xFFFFFFFFu, x, o);
                if (lane >= o) x += t;
            }
            warp_sums[lane] = x;
        }
        __syncthreads();
        int off   = (wid > 0) ? warp_sums[wid - 1] : 0;
        int total = warp_sums[31];
        int excl  = carry + off + incl - v;
        if (i < n) { g_rowptr[i] = excl; g_wpos[i] = excl; }
        carry += total;
        __syncthreads();
    }
    if (tid == 0) g_rowptr[n] = carry;
}

__global__ void scatter_kernel(const int* __restrict__ src,
                               const int* __restrict__ dst, int e) {
    int i = blockIdx.x * blockDim.x + threadIdx.x;
    if (i < e) {
        int d = dst[i];
        int p = atomicAdd(&g_wpos[d], 1);
        g_srcsorted[p] = src[i];
    }
}

// ============ mma.sync GEMM: C[M,NOUT] = act(A)[M,256] @ B[NOUT,256]^T ============
// fp32 emulated as 3x bf16 mma.sync (hi*hi + hi*lo + lo*hi), fp32 accumulators.
// Block tile 128xBN, 8 warps (4 along M x 2 along N), warp tile 32x(BN/2).
// BN=128 (layer 0): warp covers one full head -> register-only el/er epilogue.
// BN=64  (layer 1): smem-combine el/er epilogue.
// K chunked by 64 into smem hi/lo slabs; row stride 36 words -> conflict-free
// fragment loads (bank = 4*tg + tig, and 4*(8j+tg)+tig == 4*tg+tig mod 32).

__device__ __forceinline__ void mma16816(float* d, const uint32_t* a, const uint32_t* b) {
    asm volatile(
        "mma.sync.aligned.m16n8k16.row.col.f32.bf16.bf16.f32 "
        "{%0,%1,%2,%3}, {%4,%5,%6,%7}, {%8,%9}, {%0,%1,%2,%3};"
        : "+f"(d[0]), "+f"(d[1]), "+f"(d[2]), "+f"(d[3])
        : "r"(a[0]), "r"(a[1]), "r"(a[2]), "r"(a[3]), "r"(b[0]), "r"(b[1]));
}

__device__ __forceinline__ void split2(float x, float y, uint32_t& hi, uint32_t& lo) {
    __nv_bfloat162 h = __floats2bfloat162_rn(x, y);
    __nv_bfloat162 l = __floats2bfloat162_rn(x - __bfloat162float(h.x),
                                             y - __bfloat162float(h.y));
    hi = *reinterpret_cast<uint32_t*>(&h);
    lo = *reinterpret_cast<uint32_t*>(&l);
}

template<int NOUT, int BN, int H, bool RELU>
__global__ __launch_bounds__(256, 2)
void mma_gemm_kernel(const float* __restrict__ A, const float* __restrict__ B,
                     const float* __restrict__ al, const float* __restrict__ ar,
                     float* __restrict__ C,
                     float* __restrict__ el, float* __restrict__ er, int M) {
    constexpr int K = 256, KCH = 64, SREG = 36;   // words (2 bf16) per smem row
    constexpr int JN = BN / 16;                   // n8-frag pairs per warp (j count)
    constexpr int AHI = 0;
    constexpr int ALO = 128 * SREG;
    constexpr int BHI = 2 * 128 * SREG;
    constexpr int BLO = BHI + BN * SREG;

    extern __shared__ uint32_t sw[];
    const int tid  = threadIdx.x;
    const int wid  = tid >> 5;
    const int lane = tid & 31;
    const int tg   = lane >> 2;     // 0..7
    const int tig  = lane & 3;      // 0..3
    const int rowBase = blockIdx.x * 128;
    const int colBase = blockIdx.y * BN;
    const int wm = (wid & 3) * 32;         // warp M offset in tile
    const int wn = (wid >> 2) * (BN / 2);  // warp N offset in tile

    float acc[2][JN][4];
    #pragma unroll
    for (int i = 0; i < 2; i++)
        #pragma unroll
        for (int j = 0; j < JN; j++)
            #pragma unroll
            for (int q = 0; q < 4; q++) acc[i][j][q] = 0.f;

    for (int c = 0; c < K / KCH; c++) {
        // ---- stage A chunk: 128 rows x 64 cols -> hi/lo bf16 ----
        #pragma unroll
        for (int it = 0; it < 8; it++) {
            int idx = tid + it * 256;
            int r = idx >> 4, g = idx & 15;
            int gr = rowBase + r;
            float4 v = make_float4(0.f, 0.f, 0.f, 0.f);
            if (gr < M) v = *(const float4*)(A + (size_t)gr * K + c * KCH + g * 4);
            if (RELU) {
                v.x = fmaxf(v.x, 0.f); v.y = fmaxf(v.y, 0.f);
                v.z = fmaxf(v.z, 0.f); v.w = fmaxf(v.w, 0.f);
            }
            uint32_t h0, l0, h1, l1;
            split2(v.x, v.y, h0, l0);
            split2(v.z, v.w, h1, l1);
            int base = r * SREG + g * 2;
            *reinterpret_cast<uint2*>(&sw[AHI + base]) = make_uint2(h0, h1);
            *reinterpret_cast<uint2*>(&sw[ALO + base]) = make_uint2(l0, l1);
        }
        // ---- stage B chunk: BN rows x 64 cols ----
        #pragma unroll
        for (int it = 0; it < BN / 16; it++) {
            int idx = tid + it * 256;
            int r = idx >> 4, g = idx & 15;
            float4 v = *(const float4*)(B + (size_t)(colBase + r) * K + c * KCH + g * 4);
            uint32_t h0, l0, h1, l1;
            split2(v.x, v.y, h0, l0);
            split2(v.z, v.w, h1, l1);
            int base = r * SREG + g * 2;
            *reinterpret_cast<uint2*>(&sw[BHI + base]) = make_uint2(h0, h1);
            *reinterpret_cast<uint2*>(&sw[BLO + base]) = make_uint2(l0, l1);
        }
        __syncthreads();

        #pragma unroll
        for (int ks = 0; ks < KCH / 16; ks++) {
            const int kw = ks * 8;  // word offset of this k16 step within chunk
            uint32_t ah[2][4], alr[2][4];
            #pragma unroll
            for (int i = 0; i < 2; i++) {
                int r0 = (wm + i * 16 + tg) * SREG + kw + tig;
                int r1 = r0 + 8 * SREG;
                ah[i][0]  = sw[AHI + r0];     ah[i][1]  = sw[AHI + r1];
                ah[i][2]  = sw[AHI + r0 + 4]; ah[i][3]  = sw[AHI + r1 + 4];
                alr[i][0] = sw[ALO + r0];     alr[i][1] = sw[ALO + r1];
                alr[i][2] = sw[ALO + r0 + 4]; alr[i][3] = sw[ALO + r1 + 4];
            }
            #pragma unroll
            for (int j = 0; j < JN; j++) {
                int n0 = (wn + j * 8 + tg) * SREG + kw + tig;
                uint32_t bhj[2] = { sw[BHI + n0], sw[BHI + n0 + 4] };
                uint32_t blj[2] = { sw[BLO + n0], sw[BLO + n0 + 4] };
                #pragma unroll
                for (int i = 0; i < 2; i++) {
                    mma16816(acc[i][j], ah[i],  bhj);
                    mma16816(acc[i][j], ah[i],  blj);
                    mma16816(acc[i][j], alr[i], bhj);
                }
            }
        }
        __syncthreads();
    }

    // ---- write C (fragment layout: c0,c1 @ row tg; c2,c3 @ row tg+8) ----
    #pragma unroll
    for (int i = 0; i < 2; i++) {
        int r0 = rowBase + wm + i * 16 + tg;
        #pragma unroll
        for (int j = 0; j < JN; j++) {
            int col = colBase + wn + j * 8 + 2 * tig;
            if (r0 < M)
                *(float2*)(C + (size_t)r0 * NOUT + col)
                    = make_float2(acc[i][j][0], acc[i][j][1]);
            if (r0 + 8 < M)
                *(float2*)(C + (size_t)(r0 + 8) * NOUT + col)
                    = make_float2(acc[i][j][2], acc[i][j][3]);
        }
    }

    // ---- fused el/er epilogue ----
    if constexpr (BN == 128) {
        // warp's 64 cols == exactly one head -> register-only reduction, direct store
        const int head = blockIdx.y * 2 + (wn >> 6);
        const float* alh = al + head * 64;
        const float* arh = ar + head * 64;
        #pragma unroll
        for (int i = 0; i < 2; i++) {
            float pl[2] = {0.f, 0.f}, pr[2] = {0.f, 0.f};
            #pragma unroll
            for (int j = 0; j < JN; j++) {
                int c0 = j * 8 + 2 * tig;      // within-head column
                float a0 = alh[c0], a1 = alh[c0 + 1];
                float r0 = arh[c0], r1 = arh[c0 + 1];
                pl[0] = fmaf(acc[i][j][0], a0, fmaf(acc[i][j][1], a1, pl[0]));
                pl[1] = fmaf(acc[i][j][2], a0, fmaf(acc[i][j][3], a1, pl[1]));
                pr[0] = fmaf(acc[i][j][0], r0, fmaf(acc[i][j][1], r1, pr[0]));
                pr[1] = fmaf(acc[i][j][2], r0, fmaf(acc[i][j][3], r1, pr[1]));
            }
            #pragma unroll
            for (int o = 1; o < 4; o <<= 1) {
                pl[0] += __shfl_xor_sync(0xFFFFFFFFu, pl[0], o);
                pl[1] += __shfl_xor_sync(0xFFFFFFFFu, pl[1], o);
                pr[0] += __shfl_xor_sync(0xFFFFFFFFu, pr[0], o);
                pr[1] += __shfl_xor_sync(0xFFFFFFFFu, pr[1], o);
            }
            if (tig == 0) {
                int gr = rowBase + wm + i * 16 + tg;
                if (gr < M) {
                    el[(size_t)gr * H + head] = pl[0];
                    er[(size_t)gr * H + head] = pr[0];
                }
                if (gr + 8 < M) {
                    el[(size_t)(gr + 8) * H + head] = pl[1];
                    er[(size_t)(gr + 8) * H + head] = pr[1];
                }
            }
        }
    } else {
        // BN == 64: two warps share the head's 64 cols -> smem combine
        const int head = blockIdx.y;
        const float* alh = al + head * 64;
        const float* arh = ar + head * 64;
        float* elp = (float*)sw;                    // [2][128] partials (N halves)
        float* erp = elp + 256;                     // [2][128]

        #pragma unroll
        for (int i = 0; i < 2; i++) {
            float pl[2] = {0.f, 0.f}, pr[2] = {0.f, 0.f};
            #pragma unroll
            for (int j = 0; j < JN; j++) {
                int c0 = wn + j * 8 + 2 * tig;
                float a0 = alh[c0], a1 = alh[c0 + 1];
                float r0 = arh[c0], r1 = arh[c0 + 1];
                pl[0] = fmaf(acc[i][j][0], a0, fmaf(acc[i][j][1], a1, pl[0]));
                pl[1] = fmaf(acc[i][j][2], a0, fmaf(acc[i][j][3], a1, pl[1]));
                pr[0] = fmaf(acc[i][j][0], r0, fmaf(acc[i][j][1], r1, pr[0]));
                pr[1] = fmaf(acc[i][j][2], r0, fmaf(acc[i][j][3], r1, pr[1]));
            }
            #pragma unroll
            for (int o = 1; o < 4; o <<= 1) {
                pl[0] += __shfl_xor_sync(0xFFFFFFFFu, pl[0], o);
                pl[1] += __shfl_xor_sync(0xFFFFFFFFu, pl[1], o);
                pr[0] += __shfl_xor_sync(0xFFFFFFFFu, pr[0], o);
                pr[1] += __shfl_xor_sync(0xFFFFFFFFu, pr[1], o);
            }
            if (tig == 0) {
                int half = wid >> 2;
                int r = wm + i * 16 + tg;
                elp[half * 128 + r]     = pl[0];
                erp[half * 128 + r]     = pr[0];
                elp[half * 128 + r + 8] = pl[1];
                erp[half * 128 + r + 8] = pr[1];
            }
        }
        __syncthreads();
        if (tid < 128) {
            int gr = rowBase + tid;
            if (gr < M) {
                el[(size_t)gr * H + head] = elp[tid] + elp[128 + tid];
                er[(size_t)gr * H + head] = erp[tid] + erp[128 + tid];
            }
        }
    }
}

// ---------------- per-dst-node softmax + aggregation (one warp / node) -------
// pass 1: online (max, sum) accumulation per lane + warp combine
// pass 2: recompute logit, write NORMALIZED alpha to g_e (single write)
// pass 3: weighted gather of h[src] using streamed alpha
template<int H, int D>
__global__ void agg_kernel(const float* __restrict__ Hm,
                           const float* __restrict__ el,
                           const float* __restrict__ er,
                           const float* __restrict__ bias,
                           float* __restrict__ out, int n) {
    const int F = H * D, PER = F / 32;
    int warp = threadIdx.x >> 5, lane = threadIdx.x & 31;
    int node = blockIdx.x * (blockDim.x >> 5) + warp;
    if (node >= n) return;

    const int start = g_rowptr[node];
    const int end   = g_rowptr[node + 1];

    float ern[H], mx[H], sm[H];
    #pragma unroll
    for (int h = 0; h < H; h++) {
        ern[h] = er[node * H + h];
        mx[h]  = -3.402823e38f;    // finite sentinel: keeps (m-m') subtractions NaN-free
        sm[h]  = 0.f;
    }

    // pass 1: online softmax accumulation (per lane)
    for (int pos = start + lane; pos < end; pos += 32) {
        int s = g_srcsorted[pos];
        #pragma unroll
        for (int h = 0; h < H; h++) {
            float e = el[s * H + h] + ern[h];
            e = (e >= 0.f) ? e : NEG_SLOPE * e;
            float mn = fmaxf(mx[h], e);
            sm[h] = sm[h] * __expf(mx[h] - mn) + __expf(e - mn);
            mx[h] = mn;
        }
    }
    // warp combine of (m, s) pairs
    #pragma unroll
    for (int h = 0; h < H; h++) {
        #pragma unroll
        for (int o = 16; o > 0; o >>= 1) {
            float mo = __shfl_xor_sync(0xFFFFFFFFu, mx[h], o);
            float so = __shfl_xor_sync(0xFFFFFFFFu, sm[h], o);
            float mn = fmaxf(mx[h], mo);
            sm[h] = sm[h] * __expf(mx[h] - mn) + so * __expf(mo - mn);
            mx[h] = mn;
        }
    }

    float rcp[H];
    #pragma unroll
    for (int h = 0; h < H; h++) rcp[h] = (sm[h] > 0.f) ? (1.f / sm[h]) : 0.f;

    // pass 2: recompute logit, store normalized alpha
    for (int pos = start + lane; pos < end; pos += 32) {
        int s = g_srcsorted[pos];
        #pragma unroll
        for (int h = 0; h < H; h++) {
            float e = el[s * H + h] + ern[h];
            e = (e >= 0.f) ? e : NEG_SLOPE * e;
            g_e[(size_t)pos * H + h] = __expf(e - mx[h]) * rcp[h];
        }
    }
    __syncwarp();

    const int hd = (lane * PER) / D;     // head this lane's columns belong to

    float acc[PER];
    #pragma unroll
    for (int j = 0; j < PER; j++) acc[j] = 0.f;

    // pass 3: weighted gather of h[src]
    for (int pos = start; pos < end; pos++) {
        float a = g_e[(size_t)pos * H + hd];
        int   s = g_srcsorted[pos];
        if constexpr (PER == 8) {
            const float4* hp = (const float4*)(Hm + (size_t)s * F) + lane * 2;
            float4 v0 = hp[0], v1 = hp[1];
            acc[0] = fmaf(a, v0.x, acc[0]); acc[1] = fmaf(a, v0.y, acc[1]);
            acc[2] = fmaf(a, v0.z, acc[2]); acc[3] = fmaf(a, v0.w, acc[3]);
            acc[4] = fmaf(a, v1.x, acc[4]); acc[5] = fmaf(a, v1.y, acc[5]);
            acc[6] = fmaf(a, v1.z, acc[6]); acc[7] = fmaf(a, v1.w, acc[7]);
        } else {  // PER == 2
            const float2* hp = (const float2*)(Hm + (size_t)s * F) + lane;
            float2 v = hp[0];
            acc[0] = fmaf(a, v.x, acc[0]);
            acc[1] = fmaf(a, v.y, acc[1]);
        }
    }

    #pragma unroll
    for (int j = 0; j < PER; j++)
        out[(size_t)node * F + lane * PER + j] = acc[j] + bias[lane * PER + j];
}

// ---------------- launch ----------------
extern "C" void kernel_launch(void* const* d_in, const int* in_sizes, int n_in,
                              void* d_out, int out_size) {
    const float* x   = (const float*)d_in[0];
    const int*   src = (const int*)  d_in[1];
    const int*   dst = (const int*)  d_in[2];
    const float* W0  = (const float*)d_in[3];
    const float* al0 = (const float*)d_in[4];
    const float* ar0 = (const float*)d_in[5];
    const float* b0  = (const float*)d_in[6];
    const float* W1  = (const float*)d_in[7];
    const float* al1 = (const float*)d_in[8];
    const float* ar1 = (const float*)d_in[9];
    const float* b1  = (const float*)d_in[10];
    float* out = (float*)d_out;

    int n = in_sizes[0] / IN_F;
    int e = in_sizes[1];
    if (n > MAXN) n = MAXN;
    if (e > MAXE) e = MAXE;

    float *h0, *agg0, *h1, *elp, *erp;
    int   *cntp;
    cudaGetSymbolAddress((void**)&h0,   g_h0);
    cudaGetSymbolAddress((void**)&agg0, g_agg0);
    cudaGetSymbolAddress((void**)&h1,   g_h1);
    cudaGetSymbolAddress((void**)&elp,  g_el);
    cudaGetSymbolAddress((void**)&erp,  g_er);
    cudaGetSymbolAddress((void**)&cntp, g_cnt);

    // dynamic smem: (2*128 + 2*BN) rows * 36 words * 4B
    const int SMEM0 = (2 * 128 + 2 * 128) * 36 * 4;  // 73728 (BN=128)
    const int SMEM1 = (2 * 128 + 2 * 64)  * 36 * 4;  // 55296 (BN=64)
    cudaFuncSetAttribute(mma_gemm_kernel<F0, 128, HEADS, false>,
                         cudaFuncAttributeMaxDynamicSharedMemorySize, SMEM0);
    cudaFuncSetAttribute(mma_gemm_kernel<F1, 64, 1, true>,
                         cudaFuncAttributeMaxDynamicSharedMemorySize, SMEM1);

    const int TB = 256;
    // CSR build (shared by both layers)
    cudaMemsetAsync(cntp, 0, (size_t)n * sizeof(int));
    count_kernel  <<<(e + TB - 1) / TB, TB>>>(dst, e);
    scan_kernel   <<<1, 1024>>>(n);
    scatter_kernel<<<(e + TB - 1) / TB, TB>>>(src, dst, e);

    int gtiles = (n + 127) / 128;
    // layer 0 (el/er fused into GEMM epilogue; BN=128, 2 heads per block)
    mma_gemm_kernel<F0, 128, HEADS, false><<<dim3(gtiles, F0 / 128), 256, SMEM0>>>(
        x, W0, al0, ar0, h0, elp, erp, n);
    agg_kernel<HEADS, HID><<<(n + 7) / 8, 256>>>(h0, elp, erp, b0, agg0, n);

    // layer 1 (relu fused into GEMM A-load; el/er fused into epilogue; BN=64)
    mma_gemm_kernel<F1, 64, 1, true><<<dim3(gtiles, F1 / 64), 256, SMEM1>>>(
        agg0, W1, al1, ar1, h1, elp, erp, n);
    agg_kernel<1, OUT_F><<<(n + 7) / 8, 256>>>(h1, elp, erp, b1, out, n);
}

// round 14
// speedup vs baseline: 1.0390x; 1.0390x over previous
#include <cuda_runtime.h>
#include <cuda_bf16.h>
#include <cstdint>

// Problem constants (fixed by the reference)
#define MAXN   50000
#define MAXE   800000
#define IN_F   256
#define HID    64
#define HEADS  4
#define OUT_F  64
#define F0     (HEADS*HID)   // 256
#define F1     OUT_F         // 64
#define NEG_SLOPE 0.2f

// ---------------- static scratch (no allocations allowed) ----------------
__device__ float g_h0  [(size_t)MAXN * F0];   // x @ W0^T
__device__ float g_agg0[(size_t)MAXN * F0];   // layer-0 GAT output (pre-relu)
__device__ float g_h1  [(size_t)MAXN * F1];   // relu(agg0) @ W1^T
__device__ float g_e   [(size_t)MAXE * HEADS];// per-edge normalized alpha
__device__ float g_el  [(size_t)MAXN * HEADS];
__device__ float g_er  [(size_t)MAXN * HEADS];
__device__ int   g_cnt [MAXN];
__device__ int   g_rowptr[MAXN + 1];
__device__ int   g_wpos[MAXN];
__device__ int   g_srcsorted[MAXE];           // src node id of each edge, sorted by dst

// ---------------- CSR build ----------------
__global__ void count_kernel(const int* __restrict__ dst, int e) {
    int i = blockIdx.x * blockDim.x + threadIdx.x;
    if (i < e) atomicAdd(&g_cnt[dst[i]], 1);
}

// single-block exclusive scan of g_cnt[0..n) -> g_rowptr[0..n], copy to g_wpos
__global__ void scan_kernel(int n) {
    __shared__ int warp_sums[32];
    const int tid  = threadIdx.x;
    const int lane = tid & 31;
    const int wid  = tid >> 5;
    int carry = 0;
    for (int base = 0; base < n; base += 1024) {
        int i = base + tid;
        int v = (i < n) ? g_cnt[i] : 0;
        int incl = v;
        #pragma unroll
        for (int o = 1; o < 32; o <<= 1) {
            int t = __shfl_up_sync(0xFFFFFFFFu, incl, o);
            if (lane >= o) incl += t;
        }
        if (lane == 31) warp_sums[wid] = incl;
        __syncthreads();
        if (wid == 0) {
            int x = warp_sums[lane];
            #pragma unroll
            for (int o = 1; o < 32; o <<= 1) {
                int t = __shfl_up_sync(0xFFFFFFFFu, x, o);
                if (lane >= o) x += t;
            }
            warp_sums[lane] = x;
        }
        __syncthreads();
        int off   = (wid > 0) ? warp_sums[wid - 1] : 0;
        int total = warp_sums[31];
        int excl  = carry + off + incl - v;
        if (i < n) { g_rowptr[i] = excl; g_wpos[i] = excl; }
        carry += total;
        __syncthreads();
    }
    if (tid == 0) g_rowptr[n] = carry;
}

__global__ void scatter_kernel(const int* __restrict__ src,
                               const int* __restrict__ dst, int e) {
    int i = blockIdx.x * blockDim.x + threadIdx.x;
    if (i < e) {
        int d = dst[i];
        int p = atomicAdd(&g_wpos[d], 1);
        g_srcsorted[p] = src[i];
    }
}

// ---------------- shared GEMM helpers ----------------
__device__ __forceinline__ void mma16816(float* d, const uint32_t* a, const uint32_t* b) {
    asm volatile(
        "mma.sync.aligned.m16n8k16.row.col.f32.bf16.bf16.f32 "
        "{%0,%1,%2,%3}, {%4,%5,%6,%7}, {%8,%9}, {%0,%1,%2,%3};"
        : "+f"(d[0]), "+f"(d[1]), "+f"(d[2]), "+f"(d[3])
        : "r"(a[0]), "r"(a[1]), "r"(a[2]), "r"(a[3]), "r"(b[0]), "r"(b[1]));
}

__device__ __forceinline__ void split2(float x, float y, uint32_t& hi, uint32_t& lo) {
    __nv_bfloat162 h = __floats2bfloat162_rn(x, y);
    __nv_bfloat162 l = __floats2bfloat162_rn(x - __bfloat162float(h.x),
                                             y - __bfloat162float(h.y));
    hi = *reinterpret_cast<uint32_t*>(&h);
    lo = *reinterpret_cast<uint32_t*>(&l);
}

// ============ GEMM0 (layer 0): C[M,256] = A[M,256] @ B[256,256]^T ============
// Block tile 128x128, 8 warps (4M x 2N), warp tile 32x64 (one head per warp).
// fp32 emulated as 3x bf16 mma.sync; K chunked by 64; SREG=36 conflict-free.
// Register-only el/er epilogue (warp's 64 cols == one head).
__global__ __launch_bounds__(256, 2)
void mma_gemm0_kernel(const float* __restrict__ A, const float* __restrict__ B,
                      const float* __restrict__ al, const float* __restrict__ ar,
                      float* __restrict__ C,
                      float* __restrict__ el, float* __restrict__ er, int M) {
    constexpr int NOUT = F0, BN = 128, H = HEADS;
    constexpr int K = 256, KCH = 64, SREG = 36, JN = BN / 16;
    constexpr int AHI = 0;
    constexpr int ALO = 128 * SREG;
    constexpr int BHI = 2 * 128 * SREG;
    constexpr int BLO = BHI + BN * SREG;

    extern __shared__ uint32_t sw[];
    const int tid  = threadIdx.x;
    const int wid  = tid >> 5;
    const int lane = tid & 31;
    const int tg   = lane >> 2;
    const int tig  = lane & 3;
    const int rowBase = blockIdx.x * 128;
    const int colBase = blockIdx.y * BN;
    const int wm = (wid & 3) * 32;
    const int wn = (wid >> 2) * (BN / 2);

    float acc[2][JN][4];
    #pragma unroll
    for (int i = 0; i < 2; i++)
        #pragma unroll
        for (int j = 0; j < JN; j++)
            #pragma unroll
            for (int q = 0; q < 4; q++) acc[i][j][q] = 0.f;

    for (int c = 0; c < K / KCH; c++) {
        #pragma unroll
        for (int it = 0; it < 8; it++) {
            int idx = tid + it * 256;
            int r = idx >> 4, g = idx & 15;
            int gr = rowBase + r;
            float4 v = make_float4(0.f, 0.f, 0.f, 0.f);
            if (gr < M) v = *(const float4*)(A + (size_t)gr * K + c * KCH + g * 4);
            uint32_t h0, l0, h1, l1;
            split2(v.x, v.y, h0, l0);
            split2(v.z, v.w, h1, l1);
            int base = r * SREG + g * 2;
            *reinterpret_cast<uint2*>(&sw[AHI + base]) = make_uint2(h0, h1);
            *reinterpret_cast<uint2*>(&sw[ALO + base]) = make_uint2(l0, l1);
        }
        #pragma unroll
        for (int it = 0; it < BN / 16; it++) {
            int idx = tid + it * 256;
            int r = idx >> 4, g = idx & 15;
            float4 v = *(const float4*)(B + (size_t)(colBase + r) * K + c * KCH + g * 4);
            uint32_t h0, l0, h1, l1;
            split2(v.x, v.y, h0, l0);
            split2(v.z, v.w, h1, l1);
            int base = r * SREG + g * 2;
            *reinterpret_cast<uint2*>(&sw[BHI + base]) = make_uint2(h0, h1);
            *reinterpret_cast<uint2*>(&sw[BLO + base]) = make_uint2(l0, l1);
        }
        __syncthreads();

        #pragma unroll
        for (int ks = 0; ks < KCH / 16; ks++) {
            const int kw = ks * 8;
            uint32_t ah[2][4], alr[2][4];
            #pragma unroll
            for (int i = 0; i < 2; i++) {
                int r0 = (wm + i * 16 + tg) * SREG + kw + tig;
                int r1 = r0 + 8 * SREG;
                ah[i][0]  = sw[AHI + r0];     ah[i][1]  = sw[AHI + r1];
                ah[i][2]  = sw[AHI + r0 + 4]; ah[i][3]  = sw[AHI + r1 + 4];
                alr[i][0] = sw[ALO + r0];     alr[i][1] = sw[ALO + r1];
                alr[i][2] = sw[ALO + r0 + 4]; alr[i][3] = sw[ALO + r1 + 4];
            }
            #pragma unroll
            for (int j = 0; j < JN; j++) {
                int n0 = (wn + j * 8 + tg) * SREG + kw + tig;
                uint32_t bhj[2] = { sw[BHI + n0], sw[BHI + n0 + 4] };
                uint32_t blj[2] = { sw[BLO + n0], sw[BLO + n0 + 4] };
                #pragma unroll
                for (int i = 0; i < 2; i++) {
                    mma16816(acc[i][j], ah[i],  bhj);
                    mma16816(acc[i][j], ah[i],  blj);
                    mma16816(acc[i][j], alr[i], bhj);
                }
            }
        }
        __syncthreads();
    }

    #pragma unroll
    for (int i = 0; i < 2; i++) {
        int r0 = rowBase + wm + i * 16 + tg;
        #pragma unroll
        for (int j = 0; j < JN; j++) {
            int col = colBase + wn + j * 8 + 2 * tig;
            if (r0 < M)
                *(float2*)(C + (size_t)r0 * NOUT + col)
                    = make_float2(acc[i][j][0], acc[i][j][1]);
            if (r0 + 8 < M)
                *(float2*)(C + (size_t)(r0 + 8) * NOUT + col)
                    = make_float2(acc[i][j][2], acc[i][j][3]);
        }
    }

    // register-only el/er epilogue (warp covers one head)
    {
        const int head = blockIdx.y * 2 + (wn >> 6);
        const float* alh = al + head * 64;
        const float* arh = ar + head * 64;
        #pragma unroll
        for (int i = 0; i < 2; i++) {
            float pl[2] = {0.f, 0.f}, pr[2] = {0.f, 0.f};
            #pragma unroll
            for (int j = 0; j < JN; j++) {
                int c0 = j * 8 + 2 * tig;
                float a0 = alh[c0], a1 = alh[c0 + 1];
                float r0 = arh[c0], r1 = arh[c0 + 1];
                pl[0] = fmaf(acc[i][j][0], a0, fmaf(acc[i][j][1], a1, pl[0]));
                pl[1] = fmaf(acc[i][j][2], a0, fmaf(acc[i][j][3], a1, pl[1]));
                pr[0] = fmaf(acc[i][j][0], r0, fmaf(acc[i][j][1], r1, pr[0]));
                pr[1] = fmaf(acc[i][j][2], r0, fmaf(acc[i][j][3], r1, pr[1]));
            }
            #pragma unroll
            for (int o = 1; o < 4; o <<= 1) {
                pl[0] += __shfl_xor_sync(0xFFFFFFFFu, pl[0], o);
                pl[1] += __shfl_xor_sync(0xFFFFFFFFu, pl[1], o);
                pr[0] += __shfl_xor_sync(0xFFFFFFFFu, pr[0], o);
                pr[1] += __shfl_xor_sync(0xFFFFFFFFu, pr[1], o);
            }
            if (tig == 0) {
                int gr = rowBase + wm + i * 16 + tg;
                if (gr < M) {
                    el[(size_t)gr * H + head] = pl[0];
                    er[(size_t)gr * H + head] = pr[0];
                }
                if (gr + 8 < M) {
                    el[(size_t)(gr + 8) * H + head] = pl[1];
                    er[(size_t)(gr + 8) * H + head] = pr[1];
                }
            }
        }
    }
}

// ============ GEMM1 (layer 1): C[M,64] = relu(A)[M,256] @ B[64,256]^T ============
// R12-verbatim kernel: block tile 128x64, warp tile 32x32, plain launch_bounds,
// preloaded B fragments, smem-combine el/er epilogue. H == 1.
__global__ __launch_bounds__(256)
void mma_gemm1_kernel(const float* __restrict__ A, const float* __restrict__ B,
                      const float* __restrict__ al, const float* __restrict__ ar,
                      float* __restrict__ C,
                      float* __restrict__ el, float* __restrict__ er, int M) {
    constexpr int NOUT = F1;
    constexpr int K = 256, KCH = 64, SREG = 36;
    constexpr int AHI = 0;
    constexpr int ALO = 128 * SREG;
    constexpr int BHI = 2 * 128 * SREG;
    constexpr int BLO = BHI + 64 * SREG;

    extern __shared__ uint32_t sw[];
    const int tid  = threadIdx.x;
    const int wid  = tid >> 5;
    const int lane = tid & 31;
    const int tg   = lane >> 2;
    const int tig  = lane & 3;
    const int rowBase = blockIdx.x * 128;
    const int colBase = blockIdx.y * 64;
    const int wm = (wid & 3) * 32;
    const int wn = (wid >> 2) * 32;

    float acc[2][4][4];
    #pragma unroll
    for (int i = 0; i < 2; i++)
        #pragma unroll
        for (int j = 0; j < 4; j++)
            #pragma unroll
            for (int q = 0; q < 4; q++) acc[i][j][q] = 0.f;

    for (int c = 0; c < K / KCH; c++) {
        #pragma unroll
        for (int it = 0; it < 8; it++) {
            int idx = tid + it * 256;
            int r = idx >> 4, g = idx & 15;
            int gr = rowBase + r;
            float4 v = make_float4(0.f, 0.f, 0.f, 0.f);
            if (gr < M) v = *(const float4*)(A + (size_t)gr * K + c * KCH + g * 4);
            v.x = fmaxf(v.x, 0.f); v.y = fmaxf(v.y, 0.f);
            v.z = fmaxf(v.z, 0.f); v.w = fmaxf(v.w, 0.f);
            uint32_t h0, l0, h1, l1;
            split2(v.x, v.y, h0, l0);
            split2(v.z, v.w, h1, l1);
            int base = r * SREG + g * 2;
            *reinterpret_cast<uint2*>(&sw[AHI + base]) = make_uint2(h0, h1);
            *reinterpret_cast<uint2*>(&sw[ALO + base]) = make_uint2(l0, l1);
        }
        #pragma unroll
        for (int it = 0; it < 4; it++) {
            int idx = tid + it * 256;
            int r = idx >> 4, g = idx & 15;
            float4 v = *(const float4*)(B + (size_t)(colBase + r) * K + c * KCH + g * 4);
            uint32_t h0, l0, h1, l1;
            split2(v.x, v.y, h0, l0);
            split2(v.z, v.w, h1, l1);
            int base = r * SREG + g * 2;
            *reinterpret_cast<uint2*>(&sw[BHI + base]) = make_uint2(h0, h1);
            *reinterpret_cast<uint2*>(&sw[BLO + base]) = make_uint2(l0, l1);
        }
        __syncthreads();

        #pragma unroll
        for (int ks = 0; ks < KCH / 16; ks++) {
            const int kw = ks * 8;
            uint32_t ah[2][4], alr[2][4], bh[4][2], bl[4][2];
            #pragma unroll
            for (int i = 0; i < 2; i++) {
                int r0 = (wm + i * 16 + tg) * SREG + kw + tig;
                int r1 = r0 + 8 * SREG;
                ah[i][0]  = sw[AHI + r0];     ah[i][1]  = sw[AHI + r1];
                ah[i][2]  = sw[AHI + r0 + 4]; ah[i][3]  = sw[AHI + r1 + 4];
                alr[i][0] = sw[ALO + r0];     alr[i][1] = sw[ALO + r1];
                alr[i][2] = sw[ALO + r0 + 4]; alr[i][3] = sw[ALO + r1 + 4];
            }
            #pragma unroll
            for (int j = 0; j < 4; j++) {
                int n0 = (wn + j * 8 + tg) * SREG + kw + tig;
                bh[j][0] = sw[BHI + n0]; bh[j][1] = sw[BHI + n0 + 4];
                bl[j][0] = sw[BLO + n0]; bl[j][1] = sw[BLO + n0 + 4];
            }
            #pragma unroll
            for (int i = 0; i < 2; i++)
                #pragma unroll
                for (int j = 0; j < 4; j++) {
                    mma16816(acc[i][j], ah[i], bh[j]);
                    mma16816(acc[i][j], ah[i], bl[j]);
                    mma16816(acc[i][j], alr[i], bh[j]);
                }
        }
        __syncthreads();
    }

    #pragma unroll
    for (int i = 0; i < 2; i++) {
        int r0 = rowBase + wm + i * 16 + tg;
        #pragma unroll
        for (int j = 0; j < 4; j++) {
            int col = colBase + wn + j * 8 + 2 * tig;
            if (r0 < M)
                *(float2*)(C + (size_t)r0 * NOUT + col)
                    = make_float2(acc[i][j][0], acc[i][j][1]);
            if (r0 + 8 < M)
                *(float2*)(C + (size_t)(r0 + 8) * NOUT + col)
                    = make_float2(acc[i][j][2], acc[i][j][3]);
        }
    }

    // smem-combine el/er epilogue (head 0 only; H == 1)
    {
        const float* alh = al;
        const float* arh = ar;
        float* elp = (float*)sw;
        float* erp = elp + 256;

        #pragma unroll
        for (int i = 0; i < 2; i++) {
            float pl[2] = {0.f, 0.f}, pr[2] = {0.f, 0.f};
            #pragma unroll
            for (int j = 0; j < 4; j++) {
                int c0 = wn + j * 8 + 2 * tig;
                float a0 = alh[c0], a1 = alh[c0 + 1];
                float r0 = arh[c0], r1 = arh[c0 + 1];
                pl[0] = fmaf(acc[i][j][0], a0, fmaf(acc[i][j][1], a1, pl[0]));
                pl[1] = fmaf(acc[i][j][2], a0, fmaf(acc[i][j][3], a1, pl[1]));
                pr[0] = fmaf(acc[i][j][0], r0, fmaf(acc[i][j][1], r1, pr[0]));
                pr[1] = fmaf(acc[i][j][2], r0, fmaf(acc[i][j][3], r1, pr[1]));
            }
            #pragma unroll
            for (int o = 1; o < 4; o <<= 1) {
                pl[0] += __shfl_xor_sync(0xFFFFFFFFu, pl[0], o);
                pl[1] += __shfl_xor_sync(0xFFFFFFFFu, pl[1], o);
                pr[0] += __shfl_xor_sync(0xFFFFFFFFu, pr[0], o);
                pr[1] += __shfl_xor_sync(0xFFFFFFFFu, pr[1], o);
            }
            if (tig == 0) {
                int half = wid >> 2;
                int r = wm + i * 16 + tg;
                elp[half * 128 + r]     = pl[0];
                erp[half * 128 + r]     = pr[0];
                elp[half * 128 + r + 8] = pl[1];
                erp[half * 128 + r + 8] = pr[1];
            }
        }
        __syncthreads();
        if (tid < 128) {
            int gr = rowBase + tid;
            if (gr < M) {
                el[gr] = elp[tid] + elp[128 + tid];
                er[gr] = erp[tid] + erp[128 + tid];
            }
        }
    }
}

// ---------------- per-dst-node softmax + aggregation (one warp / node) -------
// pass 1: online (max, sum) accumulation per lane + warp combine
// pass 2: recompute logit, write NORMALIZED alpha to g_e (single write)
// pass 3: weighted gather of h[src] using streamed alpha
template<int H, int D>
__global__ void agg_kernel(const float* __restrict__ Hm,
                           const float* __restrict__ el,
                           const float* __restrict__ er,
                           const float* __restrict__ bias,
                           float* __restrict__ out, int n) {
    const int F = H * D, PER = F / 32;
    int warp = threadIdx.x >> 5, lane = threadIdx.x & 31;
    int node = blockIdx.x * (blockDim.x >> 5) + warp;
    if (node >= n) return;

    const int start = g_rowptr[node];
    const int end   = g_rowptr[node + 1];

    float ern[H], mx[H], sm[H];
    #pragma unroll
    for (int h = 0; h < H; h++) {
        ern[h] = er[node * H + h];
        mx[h]  = -3.402823e38f;    // finite sentinel: keeps (m-m') subtractions NaN-free
        sm[h]  = 0.f;
    }

    // pass 1: online softmax accumulation (per lane)
    for (int pos = start + lane; pos < end; pos += 32) {
        int s = g_srcsorted[pos];
        #pragma unroll
        for (int h = 0; h < H; h++) {
            float e = el[s * H + h] + ern[h];
            e = (e >= 0.f) ? e : NEG_SLOPE * e;
            float mn = fmaxf(mx[h], e);
            sm[h] = sm[h] * __expf(mx[h] - mn) + __expf(e - mn);
            mx[h] = mn;
        }
    }
    // warp combine of (m, s) pairs
    #pragma unroll
    for (int h = 0; h < H; h++) {
        #pragma unroll
        for (int o = 16; o > 0; o >>= 1) {
            float mo = __shfl_xor_sync(0xFFFFFFFFu, mx[h], o);
            float so = __shfl_xor_sync(0xFFFFFFFFu, sm[h], o);
            float mn = fmaxf(mx[h], mo);
            sm[h] = sm[h] * __expf(mx[h] - mn) + so * __expf(mo - mn);
            mx[h] = mn;
        }
    }

    float rcp[H];
    #pragma unroll
    for (int h = 0; h < H; h++) rcp[h] = (sm[h] > 0.f) ? (1.f / sm[h]) : 0.f;

    // pass 2: recompute logit, store normalized alpha
    for (int pos = start + lane; pos < end; pos += 32) {
        int s = g_srcsorted[pos];
        #pragma unroll
        for (int h = 0; h < H; h++) {
            float e = el[s * H + h] + ern[h];
            e = (e >= 0.f) ? e : NEG_SLOPE * e;
            g_e[(size_t)pos * H + h] = __expf(e - mx[h]) * rcp[h];
        }
    }
    __syncwarp();

    const int hd = (lane * PER) / D;     // head this lane's columns belong to

    float acc[PER];
    #pragma unroll
    for (int j = 0; j < PER; j++) acc[j] = 0.f;

    // pass 3: weighted gather of h[src]
    for (int pos = start; pos < end; pos++) {
        float a = g_e[(size_t)pos * H + hd];
        int   s = g_srcsorted[pos];
        if constexpr (PER == 8) {
            const float4* hp = (const float4*)(Hm + (size_t)s * F) + lane * 2;
            float4 v0 = hp[0], v1 = hp[1];
            acc[0] = fmaf(a, v0.x, acc[0]); acc[1] = fmaf(a, v0.y, acc[1]);
            acc[2] = fmaf(a, v0.z, acc[2]); acc[3] = fmaf(a, v0.w, acc[3]);
            acc[4] = fmaf(a, v1.x, acc[4]); acc[5] = fmaf(a, v1.y, acc[5]);
            acc[6] = fmaf(a, v1.z, acc[6]); acc[7] = fmaf(a, v1.w, acc[7]);
        } else {  // PER == 2
            const float2* hp = (const float2*)(Hm + (size_t)s * F) + lane;
            float2 v = hp[0];
            acc[0] = fmaf(a, v.x, acc[0]);
            acc[1] = fmaf(a, v.y, acc[1]);
        }
    }

    #pragma unroll
    for (int j = 0; j < PER; j++)
        out[(size_t)node * F + lane * PER + j] = acc[j] + bias[lane * PER + j];
}

// ---------------- launch ----------------
extern "C" void kernel_launch(void* const* d_in, const int* in_sizes, int n_in,
                              void* d_out, int out_size) {
    const float* x   = (const float*)d_in[0];
    const int*   src = (const int*)  d_in[1];
    const int*   dst = (const int*)  d_in[2];
    const float* W0  = (const float*)d_in[3];
    const float* al0 = (const float*)d_in[4];
    const float* ar0 = (const float*)d_in[5];
    const float* b0  = (const float*)d_in[6];
    const float* W1  = (const float*)d_in[7];
    const float* al1 = (const float*)d_in[8];
    const float* ar1 = (const float*)d_in[9];
    const float* b1  = (const float*)d_in[10];
    float* out = (float*)d_out;

    int n = in_sizes[0] / IN_F;
    int e = in_sizes[1];
    if (n > MAXN) n = MAXN;
    if (e > MAXE) e = MAXE;

    float *h0, *agg0, *h1, *elp, *erp;
    int   *cntp;
    cudaGetSymbolAddress((void**)&h0,   g_h0);
    cudaGetSymbolAddress((void**)&agg0, g_agg0);
    cudaGetSymbolAddress((void**)&h1,   g_h1);
    cudaGetSymbolAddress((void**)&elp,  g_el);
    cudaGetSymbolAddress((void**)&erp,  g_er);
    cudaGetSymbolAddress((void**)&cntp, g_cnt);

    // dynamic smem: (2*128 + 2*BN) rows * 36 words * 4B
    const int SMEM0 = (2 * 128 + 2 * 128) * 36 * 4;  // 73728 (BN=128)
    const int SMEM1 = (2 * 128 + 2 * 64)  * 36 * 4;  // 55296 (BN=64)
    cudaFuncSetAttribute(mma_gemm0_kernel,
                         cudaFuncAttributeMaxDynamicSharedMemorySize, SMEM0);
    cudaFuncSetAttribute(mma_gemm1_kernel,
                         cudaFuncAttributeMaxDynamicSharedMemorySize, SMEM1);

    const int TB = 256;
    // CSR build (shared by both layers)
    cudaMemsetAsync(cntp, 0, (size_t)n * sizeof(int));
    count_kernel  <<<(e + TB - 1) / TB, TB>>>(dst, e);
    scan_kernel   <<<1, 1024>>>(n);
    scatter_kernel<<<(e + TB - 1) / TB, TB>>>(src, dst, e);

    int gtiles = (n + 127) / 128;
    // layer 0 (el/er fused into GEMM epilogue; BN=128, 2 heads per block)
    mma_gemm0_kernel<<<dim3(gtiles, F0 / 128), 256, SMEM0>>>(
        x, W0, al0, ar0, h0, elp, erp, n);
    agg_kernel<HEADS, HID><<<(n + 7) / 8, 256>>>(h0, elp, erp, b0, agg0, n);

    // layer 1 (relu fused into GEMM A-load; el/er fused into epilogue; BN=64)
    mma_gemm1_kernel<<<dim3(gtiles, F1 / 64), 256, SMEM1>>>(
        agg0, W1, al1, ar1, h1, elp, erp, n);
    agg_kernel<1, OUT_F><<<(n + 7) / 8, 256>>>(h1, elp, erp, b1, out, n);
}

// round 15
// speedup vs baseline: 1.0764x; 1.0360x over previous
#include <cuda_runtime.h>
#include <cuda_bf16.h>
#include <cstdint>

// Problem constants (fixed by the reference)
#define MAXN   50000
#define MAXE   800000
#define IN_F   256
#define HID    64
#define HEADS  4
#define OUT_F  64
#define F0     (HEADS*HID)   // 256
#define F1     OUT_F         // 64
#define NEG_SLOPE 0.2f

// ---------------- static scratch (no allocations allowed) ----------------
__device__ float g_h0  [(size_t)MAXN * F0];   // x @ W0^T
__device__ float g_agg0[(size_t)MAXN * F0];   // layer-0 GAT output (pre-relu)
__device__ float g_h1  [(size_t)MAXN * F1];   // relu(agg0) @ W1^T
__device__ float g_e   [(size_t)MAXE * HEADS];// per-edge normalized alpha
__device__ float g_el  [(size_t)MAXN * HEADS];
__device__ float g_er  [(size_t)MAXN * HEADS];
__device__ int   g_cnt [MAXN];
__device__ int   g_rowptr[MAXN + 1];
__device__ int   g_wpos[MAXN];
__device__ int   g_srcsorted[MAXE];           // src node id of each edge, sorted by dst

// ---------------- CSR build ----------------
__global__ void count_kernel(const int* __restrict__ dst, int e) {
    int i = blockIdx.x * blockDim.x + threadIdx.x;
    if (i < e) atomicAdd(&g_cnt[dst[i]], 1);
}

// single-block exclusive scan of g_cnt[0..n) -> g_rowptr[0..n], copy to g_wpos
__global__ void scan_kernel(int n) {
    __shared__ int warp_sums[32];
    const int tid  = threadIdx.x;
    const int lane = tid & 31;
    const int wid  = tid >> 5;
    int carry = 0;
    for (int base = 0; base < n; base += 1024) {
        int i = base + tid;
        int v = (i < n) ? g_cnt[i] : 0;
        int incl = v;
        #pragma unroll
        for (int o = 1; o < 32; o <<= 1) {
            int t = __shfl_up_sync(0xFFFFFFFFu, incl, o);
            if (lane >= o) incl += t;
        }
        if (lane == 31) warp_sums[wid] = incl;
        __syncthreads();
        if (wid == 0) {
            int x = warp_sums[lane];
            #pragma unroll
            for (int o = 1; o < 32; o <<= 1) {
                int t = __shfl_up_sync(0xFFFFFFFFu, x, o);
                if (lane >= o) x += t;
            }
            warp_sums[lane] = x;
        }
        __syncthreads();
        int off   = (wid > 0) ? warp_sums[wid - 1] : 0;
        int total = warp_sums[31];
        int excl  = carry + off + incl - v;
        if (i < n) { g_rowptr[i] = excl; g_wpos[i] = excl; }
        carry += total;
        __syncthreads();
    }
    if (tid == 0) g_rowptr[n] = carry;
}

__global__ void scatter_kernel(const int* __restrict__ src,
                               const int* __restrict__ dst, int e) {
    int i = blockIdx.x * blockDim.x + threadIdx.x;
    if (i < e) {
        int d = dst[i];
        int p = atomicAdd(&g_wpos[d], 1);
        g_srcsorted[p] = src[i];
    }
}

// ---------------- shared GEMM helpers ----------------
__device__ __forceinline__ void mma16816(float* d, const uint32_t* a, const uint32_t* b) {
    asm volatile(
        "mma.sync.aligned.m16n8k16.row.col.f32.bf16.bf16.f32 "
        "{%0,%1,%2,%3}, {%4,%5,%6,%7}, {%8,%9}, {%0,%1,%2,%3};"
        : "+f"(d[0]), "+f"(d[1]), "+f"(d[2]), "+f"(d[3])
        : "r"(a[0]), "r"(a[1]), "r"(a[2]), "r"(a[3]), "r"(b[0]), "r"(b[1]));
}

__device__ __forceinline__ void split2(float x, float y, uint32_t& hi, uint32_t& lo) {
    __nv_bfloat162 h = __floats2bfloat162_rn(x, y);
    __nv_bfloat162 l = __floats2bfloat162_rn(x - __bfloat162float(h.x),
                                             y - __bfloat162float(h.y));
    hi = *reinterpret_cast<uint32_t*>(&h);
    lo = *reinterpret_cast<uint32_t*>(&l);
}

// ============ GEMM0 (layer 0): C[M,256] = A[M,256] @ B[256,256]^T ============
// Block tile 128x128, 8 warps (4M x 2N), warp tile 32x64 (one head per warp).
// fp32 emulated as 3x bf16 mma.sync; K chunked by 64; SREG=36 conflict-free.
// Register-only el/er epilogue (warp's 64 cols == one head).
__global__ __launch_bounds__(256, 2)
void mma_gemm0_kernel(const float* __restrict__ A, const float* __restrict__ B,
                      const float* __restrict__ al, const float* __restrict__ ar,
                      float* __restrict__ C,
                      float* __restrict__ el, float* __restrict__ er, int M) {
    constexpr int NOUT = F0, BN = 128, H = HEADS;
    constexpr int K = 256, KCH = 64, SREG = 36, JN = BN / 16;
    constexpr int AHI = 0;
    constexpr int ALO = 128 * SREG;
    constexpr int BHI = 2 * 128 * SREG;
    constexpr int BLO = BHI + BN * SREG;

    extern __shared__ uint32_t sw[];
    const int tid  = threadIdx.x;
    const int wid  = tid >> 5;
    const int lane = tid & 31;
    const int tg   = lane >> 2;
    const int tig  = lane & 3;
    const int rowBase = blockIdx.x * 128;
    const int colBase = blockIdx.y * BN;
    const int wm = (wid & 3) * 32;
    const int wn = (wid >> 2) * (BN / 2);

    float acc[2][JN][4];
    #pragma unroll
    for (int i = 0; i < 2; i++)
        #pragma unroll
        for (int j = 0; j < JN; j++)
            #pragma unroll
            for (int q = 0; q < 4; q++) acc[i][j][q] = 0.f;

    for (int c = 0; c < K / KCH; c++) {
        #pragma unroll
        for (int it = 0; it < 8; it++) {
            int idx = tid + it * 256;
            int r = idx >> 4, g = idx & 15;
            int gr = rowBase + r;
            float4 v = make_float4(0.f, 0.f, 0.f, 0.f);
            if (gr < M) v = *(const float4*)(A + (size_t)gr * K + c * KCH + g * 4);
            uint32_t h0, l0, h1, l1;
            split2(v.x, v.y, h0, l0);
            split2(v.z, v.w, h1, l1);
            int base = r * SREG + g * 2;
            *reinterpret_cast<uint2*>(&sw[AHI + base]) = make_uint2(h0, h1);
            *reinterpret_cast<uint2*>(&sw[ALO + base]) = make_uint2(l0, l1);
        }
        #pragma unroll
        for (int it = 0; it < BN / 16; it++) {
            int idx = tid + it * 256;
            int r = idx >> 4, g = idx & 15;
            float4 v = *(const float4*)(B + (size_t)(colBase + r) * K + c * KCH + g * 4);
            uint32_t h0, l0, h1, l1;
            split2(v.x, v.y, h0, l0);
            split2(v.z, v.w, h1, l1);
            int base = r * SREG + g * 2;
            *reinterpret_cast<uint2*>(&sw[BHI + base]) = make_uint2(h0, h1);
            *reinterpret_cast<uint2*>(&sw[BLO + base]) = make_uint2(l0, l1);
        }
        __syncthreads();

        #pragma unroll
        for (int ks = 0; ks < KCH / 16; ks++) {
            const int kw = ks * 8;
            uint32_t ah[2][4], alr[2][4];
            #pragma unroll
            for (int i = 0; i < 2; i++) {
                int r0 = (wm + i * 16 + tg) * SREG + kw + tig;
                int r1 = r0 + 8 * SREG;
                ah[i][0]  = sw[AHI + r0];     ah[i][1]  = sw[AHI + r1];
                ah[i][2]  = sw[AHI + r0 + 4]; ah[i][3]  = sw[AHI + r1 + 4];
                alr[i][0] = sw[ALO + r0];     alr[i][1] = sw[ALO + r1];
                alr[i][2] = sw[ALO + r0 + 4]; alr[i][3] = sw[ALO + r1 + 4];
            }
            #pragma unroll
            for (int j = 0; j < JN; j++) {
                int n0 = (wn + j * 8 + tg) * SREG + kw + tig;
                uint32_t bhj[2] = { sw[BHI + n0], sw[BHI + n0 + 4] };
                uint32_t blj[2] = { sw[BLO + n0], sw[BLO + n0 + 4] };
                #pragma unroll
                for (int i = 0; i < 2; i++) {
                    mma16816(acc[i][j], ah[i],  bhj);
                    mma16816(acc[i][j], ah[i],  blj);
                    mma16816(acc[i][j], alr[i], bhj);
                }
            }
        }
        __syncthreads();
    }

    #pragma unroll
    for (int i = 0; i < 2; i++) {
        int r0 = rowBase + wm + i * 16 + tg;
        #pragma unroll
        for (int j = 0; j < JN; j++) {
            int col = colBase + wn + j * 8 + 2 * tig;
            if (r0 < M)
                *(float2*)(C + (size_t)r0 * NOUT + col)
                    = make_float2(acc[i][j][0], acc[i][j][1]);
            if (r0 + 8 < M)
                *(float2*)(C + (size_t)(r0 + 8) * NOUT + col)
                    = make_float2(acc[i][j][2], acc[i][j][3]);
        }
    }

    // register-only el/er epilogue (warp covers one head)
    {
        const int head = blockIdx.y * 2 + (wn >> 6);
        const float* alh = al + head * 64;
        const float* arh = ar + head * 64;
        #pragma unroll
        for (int i = 0; i < 2; i++) {
            float pl[2] = {0.f, 0.f}, pr[2] = {0.f, 0.f};
            #pragma unroll
            for (int j = 0; j < JN; j++) {
                int c0 = j * 8 + 2 * tig;
                float a0 = alh[c0], a1 = alh[c0 + 1];
                float r0 = arh[c0], r1 = arh[c0 + 1];
                pl[0] = fmaf(acc[i][j][0], a0, fmaf(acc[i][j][1], a1, pl[0]));
                pl[1] = fmaf(acc[i][j][2], a0, fmaf(acc[i][j][3], a1, pl[1]));
                pr[0] = fmaf(acc[i][j][0], r0, fmaf(acc[i][j][1], r1, pr[0]));
                pr[1] = fmaf(acc[i][j][2], r0, fmaf(acc[i][j][3], r1, pr[1]));
            }
            #pragma unroll
            for (int o = 1; o < 4; o <<= 1) {
                pl[0] += __shfl_xor_sync(0xFFFFFFFFu, pl[0], o);
                pl[1] += __shfl_xor_sync(0xFFFFFFFFu, pl[1], o);
                pr[0] += __shfl_xor_sync(0xFFFFFFFFu, pr[0], o);
                pr[1] += __shfl_xor_sync(0xFFFFFFFFu, pr[1], o);
            }
            if (tig == 0) {
                int gr = rowBase + wm + i * 16 + tg;
                if (gr < M) {
                    el[(size_t)gr * H + head] = pl[0];
                    er[(size_t)gr * H + head] = pr[0];
                }
                if (gr + 8 < M) {
                    el[(size_t)(gr + 8) * H + head] = pl[1];
                    er[(size_t)(gr + 8) * H + head] = pr[1];
                }
            }
        }
    }
}

// ============ GEMM1 (layer 1): C[M,64] = relu(A)[M,256] @ B[64,256]^T ============
// R12-verbatim kernel: block tile 128x64, warp tile 32x32, plain launch_bounds,
// preloaded B fragments, smem-combine el/er epilogue. H == 1.
__global__ __launch_bounds__(256)
void mma_gemm1_kernel(const float* __restrict__ A, const float* __restrict__ B,
                      const float* __restrict__ al, const float* __restrict__ ar,
                      float* __restrict__ C,
                      float* __restrict__ el, float* __restrict__ er, int M) {
    constexpr int NOUT = F1;
    constexpr int K = 256, KCH = 64, SREG = 36;
    constexpr int AHI = 0;
    constexpr int ALO = 128 * SREG;
    constexpr int BHI = 2 * 128 * SREG;
    constexpr int BLO = BHI + 64 * SREG;

    extern __shared__ uint32_t sw[];
    const int tid  = threadIdx.x;
    const int wid  = tid >> 5;
    const int lane = tid & 31;
    const int tg   = lane >> 2;
    const int tig  = lane & 3;
    const int rowBase = blockIdx.x * 128;
    const int colBase = blockIdx.y * 64;
    const int wm = (wid & 3) * 32;
    const int wn = (wid >> 2) * 32;

    float acc[2][4][4];
    #pragma unroll
    for (int i = 0; i < 2; i++)
        #pragma unroll
        for (int j = 0; j < 4; j++)
            #pragma unroll
            for (int q = 0; q < 4; q++) acc[i][j][q] = 0.f;

    for (int c = 0; c < K / KCH; c++) {
        #pragma unroll
        for (int it = 0; it < 8; it++) {
            int idx = tid + it * 256;
            int r = idx >> 4, g = idx & 15;
            int gr = rowBase + r;
            float4 v = make_float4(0.f, 0.f, 0.f, 0.f);
            if (gr < M) v = *(const float4*)(A + (size_t)gr * K + c * KCH + g * 4);
            v.x = fmaxf(v.x, 0.f); v.y = fmaxf(v.y, 0.f);
            v.z = fmaxf(v.z, 0.f); v.w = fmaxf(v.w, 0.f);
            uint32_t h0, l0, h1, l1;
            split2(v.x, v.y, h0, l0);
            split2(v.z, v.w, h1, l1);
            int base = r * SREG + g * 2;
            *reinterpret_cast<uint2*>(&sw[AHI + base]) = make_uint2(h0, h1);
            *reinterpret_cast<uint2*>(&sw[ALO + base]) = make_uint2(l0, l1);
        }
        #pragma unroll
        for (int it = 0; it < 4; it++) {
            int idx = tid + it * 256;
            int r = idx >> 4, g = idx & 15;
            float4 v = *(const float4*)(B + (size_t)(colBase + r) * K + c * KCH + g * 4);
            uint32_t h0, l0, h1, l1;
            split2(v.x, v.y, h0, l0);
            split2(v.z, v.w, h1, l1);
            int base = r * SREG + g * 2;
            *reinterpret_cast<uint2*>(&sw[BHI + base]) = make_uint2(h0, h1);
            *reinterpret_cast<uint2*>(&sw[BLO + base]) = make_uint2(l0, l1);
        }
        __syncthreads();

        #pragma unroll
        for (int ks = 0; ks < KCH / 16; ks++) {
            const int kw = ks * 8;
            uint32_t ah[2][4], alr[2][4], bh[4][2], bl[4][2];
            #pragma unroll
            for (int i = 0; i < 2; i++) {
                int r0 = (wm + i * 16 + tg) * SREG + kw + tig;
                int r1 = r0 + 8 * SREG;
                ah[i][0]  = sw[AHI + r0];     ah[i][1]  = sw[AHI + r1];
                ah[i][2]  = sw[AHI + r0 + 4]; ah[i][3]  = sw[AHI + r1 + 4];
                alr[i][0] = sw[ALO + r0];     alr[i][1] = sw[ALO + r1];
                alr[i][2] = sw[ALO + r0 + 4]; alr[i][3] = sw[ALO + r1 + 4];
            }
            #pragma unroll
            for (int j = 0; j < 4; j++) {
                int n0 = (wn + j * 8 + tg) * SREG + kw + tig;
                bh[j][0] = sw[BHI + n0]; bh[j][1] = sw[BHI + n0 + 4];
                bl[j][0] = sw[BLO + n0]; bl[j][1] = sw[BLO + n0 + 4];
            }
            #pragma unroll
            for (int i = 0; i < 2; i++)
                #pragma unroll
                for (int j = 0; j < 4; j++) {
                    mma16816(acc[i][j], ah[i], bh[j]);
                    mma16816(acc[i][j], ah[i], bl[j]);
                    mma16816(acc[i][j], alr[i], bh[j]);
                }
        }
        __syncthreads();
    }

    #pragma unroll
    for (int i = 0; i < 2; i++) {
        int r0 = rowBase + wm + i * 16 + tg;
        #pragma unroll
        for (int j = 0; j < 4; j++) {
            int col = colBase + wn + j * 8 + 2 * tig;
            if (r0 < M)
                *(float2*)(C + (size_t)r0 * NOUT + col)
                    = make_float2(acc[i][j][0], acc[i][j][1]);
            if (r0 + 8 < M)
                *(float2*)(C + (size_t)(r0 + 8) * NOUT + col)
                    = make_float2(acc[i][j][2], acc[i][j][3]);
        }
    }

    // smem-combine el/er epilogue (head 0 only; H == 1)
    {
        const float* alh = al;
        const float* arh = ar;
        float* elp = (float*)sw;
        float* erp = elp + 256;

        #pragma unroll
        for (int i = 0; i < 2; i++) {
            float pl[2] = {0.f, 0.f}, pr[2] = {0.f, 0.f};
            #pragma unroll
            for (int j = 0; j < 4; j++) {
                int c0 = wn + j * 8 + 2 * tig;
                float a0 = alh[c0], a1 = alh[c0 + 1];
                float r0 = arh[c0], r1 = arh[c0 + 1];
                pl[0] = fmaf(acc[i][j][0], a0, fmaf(acc[i][j][1], a1, pl[0]));
                pl[1] = fmaf(acc[i][j][2], a0, fmaf(acc[i][j][3], a1, pl[1]));
                pr[0] = fmaf(acc[i][j][0], r0, fmaf(acc[i][j][1], r1, pr[0]));
                pr[1] = fmaf(acc[i][j][2], r0, fmaf(acc[i][j][3], r1, pr[1]));
            }
            #pragma unroll
            for (int o = 1; o < 4; o <<= 1) {
                pl[0] += __shfl_xor_sync(0xFFFFFFFFu, pl[0], o);
                pl[1] += __shfl_xor_sync(0xFFFFFFFFu, pl[1], o);
                pr[0] += __shfl_xor_sync(0xFFFFFFFFu, pr[0], o);
                pr[1] += __shfl_xor_sync(0xFFFFFFFFu, pr[1], o);
            }
            if (tig == 0) {
                int half = wid >> 2;
                int r = wm + i * 16 + tg;
                elp[half * 128 + r]     = pl[0];
                erp[half * 128 + r]     = pr[0];
                elp[half * 128 + r + 8] = pl[1];
                erp[half * 128 + r + 8] = pr[1];
            }
        }
        __syncthreads();
        if (tid < 128) {
            int gr = rowBase + tid;
            if (gr < M) {
                el[gr] = elp[tid] + elp[128 + tid];
                er[gr] = erp[tid] + erp[128 + tid];
            }
        }
    }
}

// ---------------- per-dst-node softmax + aggregation (one warp / node) -------
// pass 1: online (max, sum) accumulation per lane + warp combine
// pass 2: recompute logit, write NORMALIZED alpha to g_e (single write)
// pass 3: weighted gather of h[src] using streamed alpha
template<int H, int D>
__global__ void agg_kernel(const float* __restrict__ Hm,
                           const float* __restrict__ el,
                           const float* __restrict__ er,
                           const float* __restrict__ bias,
                           float* __restrict__ out, int n) {
    const int F = H * D, PER = F / 32;
    int warp = threadIdx.x >> 5, lane = threadIdx.x & 31;
    int node = blockIdx.x * (blockDim.x >> 5) + warp;
    if (node >= n) return;

    const int start = g_rowptr[node];
    const int end   = g_rowptr[node + 1];

    float ern[H], mx[H], sm[H];
    #pragma unroll
    for (int h = 0; h < H; h++) {
        ern[h] = er[node * H + h];
        mx[h]  = -3.402823e38f;    // finite sentinel: keeps (m-m') subtractions NaN-free
        sm[h]  = 0.f;
    }

    // pass 1: online softmax accumulation (per lane)
    for (int pos = start + lane; pos < end; pos += 32) {
        int s = g_srcsorted[pos];
        #pragma unroll
        for (int h = 0; h < H; h++) {
            float e = el[s * H + h] + ern[h];
            e = (e >= 0.f) ? e : NEG_SLOPE * e;
            float mn = fmaxf(mx[h], e);
            sm[h] = sm[h] * __expf(mx[h] - mn) + __expf(e - mn);
            mx[h] = mn;
        }
    }
    // warp combine of (m, s) pairs
    #pragma unroll
    for (int h = 0; h < H; h++) {
        #pragma unroll
        for (int o = 16; o > 0; o >>= 1) {
            float mo = __shfl_xor_sync(0xFFFFFFFFu, mx[h], o);
            float so = __shfl_xor_sync(0xFFFFFFFFu, sm[h], o);
            float mn = fmaxf(mx[h], mo);
            sm[h] = sm[h] * __expf(mx[h] - mn) + so * __expf(mo - mn);
            mx[h] = mn;
        }
    }

    float rcp[H];
    #pragma unroll
    for (int h = 0; h < H; h++) rcp[h] = (sm[h] > 0.f) ? (1.f / sm[h]) : 0.f;

    // pass 2: recompute logit, store normalized alpha
    for (int pos = start + lane; pos < end; pos += 32) {
        int s = g_srcsorted[pos];
        #pragma unroll
        for (int h = 0; h < H; h++) {
            float e = el[s * H + h] + ern[h];
            e = (e >= 0.f) ? e : NEG_SLOPE * e;
            g_e[(size_t)pos * H + h] = __expf(e - mx[h]) * rcp[h];
        }
    }
    __syncwarp();

    const int hd = (lane * PER) / D;     // head this lane's columns belong to

    float acc[PER];
    #pragma unroll
    for (int j = 0; j < PER; j++) acc[j] = 0.f;

    // pass 3: weighted gather of h[src]
    for (int pos = start; pos < end; pos++) {
        float a = g_e[(size_t)pos * H + hd];
        int   s = g_srcsorted[pos];
        if constexpr (PER == 8) {
            const float4* hp = (const float4*)(Hm + (size_t)s * F) + lane * 2;
            float4 v0 = hp[0], v1 = hp[1];
            acc[0] = fmaf(a, v0.x, acc[0]); acc[1] = fmaf(a, v0.y, acc[1]);
            acc[2] = fmaf(a, v0.z, acc[2]); acc[3] = fmaf(a, v0.w, acc[3]);
            acc[4] = fmaf(a, v1.x, acc[4]); acc[5] = fmaf(a, v1.y, acc[5]);
            acc[6] = fmaf(a, v1.z, acc[6]); acc[7] = fmaf(a, v1.w, acc[7]);
        } else {  // PER == 2
            const float2* hp = (const float2*)(Hm + (size_t)s * F) + lane;
            float2 v = hp[0];
            acc[0] = fmaf(a, v.x, acc[0]);
            acc[1] = fmaf(a, v.y, acc[1]);
        }
    }

    #pragma unroll
    for (int j = 0; j < PER; j++)
        out[(size_t)node * F + lane * PER + j] = acc[j] + bias[lane * PER + j];
}

// ---------------- launch ----------------
extern "C" void kernel_launch(void* const* d_in, const int* in_sizes, int n_in,
                              void* d_out, int out_size) {
    const float* x   = (const float*)d_in[0];
    const int*   src = (const int*)  d_in[1];
    const int*   dst = (const int*)  d_in[2];
    const float* W0  = (const float*)d_in[3];
    const float* al0 = (const float*)d_in[4];
    const float* ar0 = (const float*)d_in[5];
    const float* b0  = (const float*)d_in[6];
    const float* W1  = (const float*)d_in[7];
    const float* al1 = (const float*)d_in[8];
    const float* ar1 = (const float*)d_in[9];
    const float* b1  = (const float*)d_in[10];
    float* out = (float*)d_out;

    int n = in_sizes[0] / IN_F;
    int e = in_sizes[1];
    if (n > MAXN) n = MAXN;
    if (e > MAXE) e = MAXE;

    float *h0, *agg0, *h1, *elp, *erp;
    int   *cntp;
    cudaGetSymbolAddress((void**)&h0,   g_h0);
    cudaGetSymbolAddress((void**)&agg0, g_agg0);
    cudaGetSymbolAddress((void**)&h1,   g_h1);
    cudaGetSymbolAddress((void**)&elp,  g_el);
    cudaGetSymbolAddress((void**)&erp,  g_er);
    cudaGetSymbolAddress((void**)&cntp, g_cnt);

    // dynamic smem: (2*128 + 2*BN) rows * 36 words * 4B
    const int SMEM0 = (2 * 128 + 2 * 128) * 36 * 4;  // 73728 (BN=128)
    const int SMEM1 = (2 * 128 + 2 * 64)  * 36 * 4;  // 55296 (BN=64)
    cudaFuncSetAttribute(mma_gemm0_kernel,
                         cudaFuncAttributeMaxDynamicSharedMemorySize, SMEM0);
    cudaFuncSetAttribute(mma_gemm1_kernel,
                         cudaFuncAttributeMaxDynamicSharedMemorySize, SMEM1);

    // one-time host-side stream/event objects (no device memory involved)
    static cudaStream_t s2 = nullptr;
    static cudaEvent_t evFork = nullptr, evJoin = nullptr;
    if (s2 == nullptr) {
        cudaStreamCreateWithFlags(&s2, cudaStreamNonBlocking);
        cudaEventCreateWithFlags(&evFork, cudaEventDisableTiming);
        cudaEventCreateWithFlags(&evJoin, cudaEventDisableTiming);
    }

    const int TB = 256;
    int gtiles = (n + 127) / 128;

    // ---- fork: CSR build on s2, concurrent with GEMM0 on the main stream ----
    cudaEventRecord(evFork, 0);
    cudaStreamWaitEvent(s2, evFork, 0);

    cudaMemsetAsync(cntp, 0, (size_t)n * sizeof(int), s2);
    count_kernel  <<<(e + TB - 1) / TB, TB, 0, s2>>>(dst, e);
    scan_kernel   <<<1, 1024, 0, s2>>>(n);
    scatter_kernel<<<(e + TB - 1) / TB, TB, 0, s2>>>(src, dst, e);
    cudaEventRecord(evJoin, s2);

    // layer 0 GEMM (el/er fused into epilogue; BN=128, 2 heads per block)
    mma_gemm0_kernel<<<dim3(gtiles, F0 / 128), 256, SMEM0>>>(
        x, W0, al0, ar0, h0, elp, erp, n);

    // ---- join: agg0 needs both GEMM0 and the CSR ----
    cudaStreamWaitEvent(0, evJoin, 0);
    agg_kernel<HEADS, HID><<<(n + 7) / 8, 256>>>(h0, elp, erp, b0, agg0, n);

    // layer 1 (relu fused into GEMM A-load; el/er fused into epilogue; BN=64)
    mma_gemm1_kernel<<<dim3(gtiles, F1 / 64), 256, SMEM1>>>(
        agg0, W1, al1, ar1, h1, elp, erp, n);
    agg_kernel<1, OUT_F><<<(n + 7) / 8, 256>>>(h1, elp, erp, b1, out, n);
}